// round 11
// baseline (speedup 1.0000x reference)
#include <cuda_runtime.h>

#define D1 32
#define D2 16
#define NMAX 100000
#define NBLK 888          // <= 148 SM x 6 resident blocks; all co-resident
#define TB   256
#define FULL 0xffffffffu

// ---------------- scratch (device globals; no allocation allowed) -------------
__device__ __align__(16) float g_q   [NMAX * D1];
__device__ __align__(16) float g_k   [NMAX * D1];
__device__ __align__(16) float g_v   [NMAX * D1];
__device__ __align__(16) float g_skip[NMAX * D1];
__device__ __align__(16) float g_acc [NMAX * D1];
__device__ __align__(16) float g_q2  [NMAX * D2];
__device__ __align__(16) float g_k2  [NMAX * D2];
__device__ __align__(16) float g_v2  [NMAX * D2];
__device__ __align__(16) float g_sk2 [NMAX * D2];
__device__ float g_sum [NMAX];

// ---------------- software grid barrier --------------------------------------
__device__ int               g_bar_count = 0;
__device__ volatile unsigned g_bar_gen   = 0;

__device__ __forceinline__ void grid_sync() {
    __threadfence();                       // all this thread's writes visible
    __syncthreads();                       // whole block has fenced
    if (threadIdx.x == 0) {
        unsigned gen = g_bar_gen;
        int arrived = atomicAdd(&g_bar_count, 1);
        if (arrived == NBLK - 1) {
            g_bar_count = 0;               // reset before release
            __threadfence();
            g_bar_gen = gen + 1;           // release everyone
        } else {
            while (g_bar_gen == gen) __nanosleep(64);
        }
        __threadfence();
    }
    __syncthreads();
}

__device__ __forceinline__ void redAdd4(float4* p, float a, float b, float c, float d) {
    asm volatile("red.global.add.v4.f32 [%0], {%1,%2,%3,%4};"
                 :: "l"(p), "f"(a), "f"(b), "f"(c), "f"(d) : "memory");
}

// ---------------- the whole network in one persistent kernel ------------------
__global__ __launch_bounds__(TB, 8) void gnn_kernel(
        const int* __restrict__ src, const int* __restrict__ dst,
        const float* __restrict__ x,
        const float* __restrict__ Wq1, const float* __restrict__ bq1,
        const float* __restrict__ Wk1, const float* __restrict__ bk1,
        const float* __restrict__ Wv1, const float* __restrict__ bv1,
        const float* __restrict__ Ws1, const float* __restrict__ bs1,
        const float* __restrict__ Wq2, const float* __restrict__ bq2,
        const float* __restrict__ Wk2, const float* __restrict__ bk2,
        const float* __restrict__ Wv2, const float* __restrict__ bv2,
        const float* __restrict__ Ws2, const float* __restrict__ bs2,
        const float* __restrict__ Wo,  const float* __restrict__ bo,
        float* __restrict__ out,
        int N, int E, float s1, float s2) {
    const int tid     = threadIdx.x;
    const int lane    = tid & 31;
    const int gt      = blockIdx.x * TB + tid;
    const int gstride = NBLK * TB;                 // 227328: divisible by 32
    const int gwarp   = gt >> 5;
    const int nwarps  = gstride >> 5;              // 7104

    // ======== P0: layer-1 projection (warp per node, shfl-broadcast x) =======
    {
        float cbq = __ldg(bq1 + lane), cbk = __ldg(bk1 + lane);
        float cbv = __ldg(bv1 + lane), cbs = __ldg(bs1 + lane);
        for (int node = gwarp; node < N; node += nwarps) {
            float xj = x[(size_t)node * D1 + lane];
            float aq = cbq, ak = cbk, av = cbv, as_ = cbs;
            #pragma unroll
            for (int i = 0; i < D1; i++) {
                float xi = __shfl_sync(FULL, xj, i);
                aq  = fmaf(xi, __ldg(Wq1 + i * D1 + lane), aq);
                ak  = fmaf(xi, __ldg(Wk1 + i * D1 + lane), ak);
                av  = fmaf(xi, __ldg(Wv1 + i * D1 + lane), av);
                as_ = fmaf(xi, __ldg(Ws1 + i * D1 + lane), as_);
            }
            int o = node * D1 + lane;
            g_q[o] = aq; g_k[o] = ak; g_v[o] = av; g_skip[o] = as_;
            g_acc[o] = 0.0f;
            if (lane == 0) g_sum[node] = 0.0f;
        }
    }
    grid_sync();

    // ======== P1: layer-1 edge pass (4 lanes/edge, grid-stride) ==============
    {
        int total = E << 2;
        int pad = ((total + gstride - 1) / gstride) * gstride;
        for (int t = gt; t < pad; t += gstride) {
            bool act = t < total;
            int e = act ? (t >> 2) : 0;
            int sub = t & 3;
            int s = src[e], d = dst[e];
            const float4* qr = (const float4*)(g_q + (size_t)d * D1);
            const float4* kr = (const float4*)(g_k + (size_t)s * D1);
            float4 qa = qr[sub],     ka = kr[sub];
            float4 qb = qr[4 + sub], kb = kr[4 + sub];
            float p = qa.x*ka.x + qa.y*ka.y + qa.z*ka.z + qa.w*ka.w
                    + qb.x*kb.x + qb.y*kb.y + qb.z*kb.z + qb.w*kb.w;
            p += __shfl_xor_sync(FULL, p, 1, 4);
            p += __shfl_xor_sync(FULL, p, 2, 4);
            float w = __expf(fminf(p * s1, 75.0f));
            if (act) {
                if (sub == 0) atomicAdd(g_sum + d, w);
                const float4* vr = (const float4*)(g_v + (size_t)s * D1);
                float4 va = vr[sub], vb = vr[4 + sub];
                float4* ar = (float4*)(g_acc + (size_t)d * D1);
                redAdd4(ar + sub,     va.x*w, va.y*w, va.z*w, va.w*w);
                redAdd4(ar + 4 + sub, vb.x*w, vb.y*w, vb.z*w, vb.w*w);
            }
        }
    }
    grid_sync();

    // ======== P2: finalize layer 1 + layer-2 projection (warp per node) ======
    {
        int j = lane & 15;
        bool hih = lane >= 16;
        const float* WA = hih ? Wv2 : Wq2;
        const float* WB = hih ? Ws2 : Wk2;
        float cb0 = __ldg((hih ? bv2 : bq2) + j);
        float cb1 = __ldg((hih ? bs2 : bk2) + j);
        for (int node = gwarp; node < N; node += nwarps) {
            int o = node * D1 + lane;
            float sum = __ldcg(g_sum + node);
            float h = __ldcg(g_acc + o) / (sum + 1e-16f) + __ldcg(g_skip + o);
            h = fmaxf(h, 0.0f);
            g_acc[o] = 0.0f;                       // re-init for layer-2 edges
            if (lane == 0) g_sum[node] = 0.0f;
            float a0 = cb0, a1 = cb1;
            #pragma unroll
            for (int i = 0; i < D1; i++) {
                float hi = __shfl_sync(FULL, h, i);
                a0 = fmaf(hi, __ldg(WA + i * D2 + j), a0);
                a1 = fmaf(hi, __ldg(WB + i * D2 + j), a1);
            }
            int o2 = node * D2 + j;
            if (!hih) { g_q2[o2] = a0; g_k2[o2] = a1; }
            else      { g_v2[o2] = a0; g_sk2[o2] = a1; }
        }
    }
    grid_sync();

    // ======== P3: layer-2 edge pass (4 lanes/edge, grid-stride) ==============
    {
        int total = E << 2;
        int pad = ((total + gstride - 1) / gstride) * gstride;
        for (int t = gt; t < pad; t += gstride) {
            bool act = t < total;
            int e = act ? (t >> 2) : 0;
            int sub = t & 3;
            int s = src[e], d = dst[e];
            float4 q = ((const float4*)(g_q2 + (size_t)d * D2))[sub];
            float4 k = ((const float4*)(g_k2 + (size_t)s * D2))[sub];
            float p = q.x*k.x + q.y*k.y + q.z*k.z + q.w*k.w;
            p += __shfl_xor_sync(FULL, p, 1, 4);
            p += __shfl_xor_sync(FULL, p, 2, 4);
            float w = __expf(fminf(p * s2, 75.0f));
            if (act) {
                if (sub == 0) atomicAdd(g_sum + d, w);
                float4 v = ((const float4*)(g_v2 + (size_t)s * D2))[sub];
                redAdd4(((float4*)(g_acc + (size_t)d * D2)) + sub,
                        v.x*w, v.y*w, v.z*w, v.w*w);
            }
        }
    }
    grid_sync();

    // ======== P4: finalize layer 2 + output linear (16 -> 2) =================
    {
        int total = N * D2;                        // divisible by 16
        int pad = ((total + gstride - 1) / gstride) * gstride;
        for (int t = gt; t < pad; t += gstride) {
            bool act = t < total;
            int tt = act ? t : 0;
            int node = tt >> 4;
            int i = tt & 15;
            float val = __ldcg(g_acc + tt) / (__ldcg(g_sum + node) + 1e-16f)
                      + g_sk2[tt];
            val = fmaxf(val, 0.0f);
            float p0 = val * __ldg(Wo + i * 2 + 0);
            float p1 = val * __ldg(Wo + i * 2 + 1);
            #pragma unroll
            for (int o = 8; o; o >>= 1) {
                p0 += __shfl_xor_sync(FULL, p0, o, 16);
                p1 += __shfl_xor_sync(FULL, p1, o, 16);
            }
            if (act && i == 0) {
                out[node * 2 + 0] = p0 + __ldg(bo + 0);
                out[node * 2 + 1] = p1 + __ldg(bo + 1);
            }
        }
    }
}

// ---------------- launch ------------------------------------------------------
extern "C" void kernel_launch(void* const* d_in, const int* in_sizes, int n_in,
                              void* d_out, int out_size) {
    const int*   ei  = (const int*)d_in[0];
    const float* emb = (const float*)d_in[1];
    const float *Wq1 = (const float*)d_in[2],  *bq1 = (const float*)d_in[3];
    const float *Wk1 = (const float*)d_in[4],  *bk1 = (const float*)d_in[5];
    const float *Wv1 = (const float*)d_in[6],  *bv1 = (const float*)d_in[7];
    const float *Ws1 = (const float*)d_in[8],  *bs1 = (const float*)d_in[9];
    const float *Wq2 = (const float*)d_in[10], *bq2 = (const float*)d_in[11];
    const float *Wk2 = (const float*)d_in[12], *bk2 = (const float*)d_in[13];
    const float *Wv2 = (const float*)d_in[14], *bv2 = (const float*)d_in[15];
    const float *Ws2 = (const float*)d_in[16], *bs2 = (const float*)d_in[17];
    const float *Wo  = (const float*)d_in[18], *bo  = (const float*)d_in[19];
    float* out = (float*)d_out;

    int E = in_sizes[0] / 2;
    int N = in_sizes[1] / D1;
    const int* src = ei;
    const int* dst = ei + E;

    float s1 = 1.0f / sqrtf((float)D1);
    float s2 = 1.0f / sqrtf((float)D2);

    gnn_kernel<<<NBLK, TB>>>(src, dst, emb,
                             Wq1, bq1, Wk1, bk1, Wv1, bv1, Ws1, bs1,
                             Wq2, bq2, Wk2, bk2, Wv2, bv2, Ws2, bs2,
                             Wo, bo, out, N, E, s1, s2);
}

// round 12
// speedup vs baseline: 1.1537x; 1.1537x over previous
#include <cuda_runtime.h>
#include <math_constants.h>

#define N_NODES 100000
#define N_EDGES 1600000
#define D1 32
#define D2 16
#define FULL 0xffffffffu

// ---------------- scratch (device globals; no allocation allowed) -------------
__device__ __align__(16) float g_q   [N_NODES * D1];
__device__ __align__(16) float g_k   [N_NODES * D1];
__device__ __align__(16) float g_v   [N_NODES * D1];
__device__ __align__(16) float g_skip[N_NODES * D1];
__device__ __align__(16) float g_acc [N_NODES * D1];
__device__ float g_sum [N_NODES];
__device__ __align__(16) float g_sk2 [N_NODES * D2];

// ---------------- helpers ----------------------------------------------------
__device__ __forceinline__ void redAdd4(float4* p, float a, float b, float c, float d) {
    asm volatile("red.global.add.v4.f32 [%0], {%1,%2,%3,%4};"
                 :: "l"(p), "f"(a), "f"(b), "f"(c), "f"(d) : "memory");
}

// ---------------- layer-1 projection, fused with acc/sum zeroing -------------
// Reads ONLY harness inputs -> full compute pre-sync; sync guards the stores
// (previous graph replay's finalize2_out reads g_acc/g_sum).
__global__ __launch_bounds__(256) void proj1_kernel(
        const float* __restrict__ x,
        const float* __restrict__ Wq, const float* __restrict__ bq,
        const float* __restrict__ Wk, const float* __restrict__ bk,
        const float* __restrict__ Wv, const float* __restrict__ bv,
        const float* __restrict__ Ws, const float* __restrict__ bs,
        int n) {
    constexpr int NPB = 256 / D1;              // 8 nodes per block
    __shared__ float sW[4][D1 * D1];
    __shared__ float sx[NPB][D1];
    int t = threadIdx.x;
    cudaTriggerProgrammaticLaunchCompletion();
    for (int i = t; i < D1 * D1; i += 256) {
        sW[0][i] = Wq[i]; sW[1][i] = Wk[i]; sW[2][i] = Wv[i]; sW[3][i] = Ws[i];
    }
    int node0 = blockIdx.x * NPB;
    for (int i = t; i < NPB * D1; i += 256) {
        int nn = node0 + (i >> 5);
        sx[i >> 5][i & 31] = (nn < n) ? x[(size_t)nn * D1 + (i & 31)] : 0.0f;
    }
    __syncthreads();
    int ln = t >> 5;
    int j  = t & 31;
    int node = node0 + ln;
    if (node >= n) { cudaGridDependencySynchronize(); return; }
    float aq = bq[j], ak = bk[j], av = bv[j], as_ = bs[j];
    #pragma unroll
    for (int i = 0; i < D1; i++) {
        float xi = sx[ln][i];
        aq  = fmaf(xi, sW[0][i * D1 + j], aq);
        ak  = fmaf(xi, sW[1][i * D1 + j], ak);
        av  = fmaf(xi, sW[2][i * D1 + j], av);
        as_ = fmaf(xi, sW[3][i * D1 + j], as_);
    }
    cudaGridDependencySynchronize();           // prev replay done with g_acc/g_sum
    int o = node * D1 + j;
    g_q[o] = aq; g_k[o] = ak; g_v[o] = av; g_skip[o] = as_;
    g_acc[o] = 0.0f;
    if (j == 0) g_sum[node] = 0.0f;
}

// ---------------- single fused edge pass (R5 form: 4 lanes/edge) -------------
template<int D>
__global__ __launch_bounds__(256) void edge_fused_kernel(
        const int* __restrict__ src, const int* __restrict__ dst,
        float scale, int nE) {
    int tid = blockIdx.x * blockDim.x + threadIdx.x;
    int e = tid >> 2, lane = tid & 3;
    cudaTriggerProgrammaticLaunchCompletion();
    if (e >= nE) { cudaGridDependencySynchronize(); return; }
    int s = src[e], d = dst[e];                // inputs: safe pre-sync
    cudaGridDependencySynchronize();           // wait for q/k/v/acc producers
    const float4* qr = (const float4*)(g_q + (size_t)d * D);
    const float4* kr = (const float4*)(g_k + (size_t)s * D);
    float acc = 0.0f;
    #pragma unroll
    for (int i = 0; i < D / 16; i++) {
        float4 a = qr[i * 4 + lane];
        float4 b = kr[i * 4 + lane];
        acc = fmaf(a.x, b.x, fmaf(a.y, b.y, fmaf(a.z, b.z, fmaf(a.w, b.w, acc))));
    }
    unsigned m = __activemask();
    acc += __shfl_xor_sync(m, acc, 1, 4);
    acc += __shfl_xor_sync(m, acc, 2, 4);
    float w = __expf(fminf(acc * scale, 75.0f));   // overflow guard only
    if (lane == 0) atomicAdd(g_sum + d, w);
    const float4* vr = (const float4*)(g_v + (size_t)s * D);
    float4*       ar = (float4*)(g_acc + (size_t)d * D);
    #pragma unroll
    for (int i = 0; i < D / 16; i++) {
        float4 t = vr[i * 4 + lane];
        redAdd4(ar + i * 4 + lane, t.x * w, t.y * w, t.z * w, t.w * w);
    }
}

// ---------------- fused: finalize layer 1 -> SMEM h -> layer-2 projection ----
__global__ __launch_bounds__(256) void fin1_proj2_kernel(
        const float* __restrict__ Wq, const float* __restrict__ bq,
        const float* __restrict__ Wk, const float* __restrict__ bk,
        const float* __restrict__ Wv, const float* __restrict__ bv,
        const float* __restrict__ Ws, const float* __restrict__ bs,
        int n) {
    constexpr int NPB = 256 / D2;              // 16 nodes per block
    __shared__ float sW[4][D1 * D2];
    __shared__ float sh[NPB][D1];
    int t = threadIdx.x;
    cudaTriggerProgrammaticLaunchCompletion();
    for (int i = t; i < D1 * D2; i += 256) {   // inputs: safe pre-sync
        sW[0][i] = Wq[i]; sW[1][i] = Wk[i]; sW[2][i] = Wv[i]; sW[3][i] = Ws[i];
    }
    cudaGridDependencySynchronize();           // wait for edge1 acc/sum
    int node0 = blockIdx.x * NPB;
    #pragma unroll
    for (int r = 0; r < 2; r++) {
        int i = t + r * 256;                   // 0..511 = 16 nodes * 32 dims
        int ln = i >> 5;
        int node = node0 + ln;
        if (node < n) {
            int o = node * D1 + (i & 31);
            float val = g_acc[o] / (g_sum[node] + 1e-16f) + g_skip[o];
            sh[ln][i & 31] = fmaxf(val, 0.0f);
            g_acc[o] = 0.0f;                   // re-init for layer-2 edge pass
            if ((i & 31) == 0) g_sum[node] = 0.0f;
        }
    }
    __syncthreads();
    // Phase B: projection 32 -> 16. thread = (node ln, j); all 4 outputs.
    int ln = t >> 4;
    int j  = t & 15;
    int node = node0 + ln;
    if (node >= n) return;
    float aq = bq[j], ak = bk[j], av = bv[j], as_ = bs[j];
    #pragma unroll
    for (int i = 0; i < D1; i++) {
        float hi = sh[ln][i];
        aq  = fmaf(hi, sW[0][i * D2 + j], aq);
        ak  = fmaf(hi, sW[1][i * D2 + j], ak);
        av  = fmaf(hi, sW[2][i * D2 + j], av);
        as_ = fmaf(hi, sW[3][i * D2 + j], as_);
    }
    // layer-2 q/k/v live in the low halves of g_q/g_k/g_v (stride D2)
    g_q[node * D2 + j] = aq;
    g_k[node * D2 + j] = ak;
    g_v[node * D2 + j] = av;
    g_sk2[node * D2 + j] = as_;
}

// ---------------- finalize layer 2 + output linear (16 -> 2), fused ----------
__global__ __launch_bounds__(256) void finalize2_out_kernel(
        const float* __restrict__ Wo, const float* __restrict__ bo,
        float* __restrict__ out, int n) {
    int tid = blockIdx.x * blockDim.x + threadIdx.x;
    cudaTriggerProgrammaticLaunchCompletion();
    int node = tid >> 4;
    int i = tid & 15;
    float w0 = __ldg(Wo + i * 2 + 0);          // inputs: safe pre-sync
    float w1 = __ldg(Wo + i * 2 + 1);
    float b0 = __ldg(bo + 0), b1 = __ldg(bo + 1);
    cudaGridDependencySynchronize();           // wait for edge2 acc/sum
    if (tid >= n * D2) return;
    float val = g_acc[tid] / (g_sum[node] + 1e-16f) + g_sk2[tid];
    val = fmaxf(val, 0.0f);
    float p0 = val * w0;
    float p1 = val * w1;
    unsigned m = __activemask();
    #pragma unroll
    for (int o = 8; o; o >>= 1) {
        p0 += __shfl_xor_sync(m, p0, o, 16);
        p1 += __shfl_xor_sync(m, p1, o, 16);
    }
    if (i == 0) {
        out[node * 2 + 0] = p0 + b0;
        out[node * 2 + 1] = p1 + b1;
    }
}

// ---------------- PDL launch helper -------------------------------------------
template<typename... Args>
static void launch_pdl(void (*fn)(Args...), int grid, int block, Args... args) {
    cudaLaunchConfig_t cfg = {};
    cfg.gridDim = dim3(grid, 1, 1);
    cfg.blockDim = dim3(block, 1, 1);
    cfg.stream = 0;
    cudaLaunchAttribute attr[1];
    attr[0].id = cudaLaunchAttributeProgrammaticStreamSerialization;
    attr[0].val.programmaticStreamSerializationAllowed = 1;
    cfg.attrs = attr;
    cfg.numAttrs = 1;
    cudaLaunchKernelEx(&cfg, fn, args...);
}

// ---------------- launch ------------------------------------------------------
extern "C" void kernel_launch(void* const* d_in, const int* in_sizes, int n_in,
                              void* d_out, int out_size) {
    const int*   ei  = (const int*)d_in[0];
    const float* emb = (const float*)d_in[1];
    const float *Wq1 = (const float*)d_in[2],  *bq1 = (const float*)d_in[3];
    const float *Wk1 = (const float*)d_in[4],  *bk1 = (const float*)d_in[5];
    const float *Wv1 = (const float*)d_in[6],  *bv1 = (const float*)d_in[7];
    const float *Ws1 = (const float*)d_in[8],  *bs1 = (const float*)d_in[9];
    const float *Wq2 = (const float*)d_in[10], *bq2 = (const float*)d_in[11];
    const float *Wk2 = (const float*)d_in[12], *bk2 = (const float*)d_in[13];
    const float *Wv2 = (const float*)d_in[14], *bv2 = (const float*)d_in[15];
    const float *Ws2 = (const float*)d_in[16], *bs2 = (const float*)d_in[17];
    const float *Wo  = (const float*)d_in[18], *bo  = (const float*)d_in[19];
    float* out = (float*)d_out;

    int E = in_sizes[0] / 2;
    int N = in_sizes[1] / D1;
    const int* src = ei;
    const int* dst = ei + E;

    const int TB = 256;
    int gP1 = (N + 7) / 8;                     // 8 nodes / block
    int gE4 = (int)(((size_t)E * 4 + TB - 1) / TB);  // 4 lanes / edge
    int gFP = (N + 15) / 16;                   // 16 nodes / block
    int gN2 = (N * D2 + TB - 1) / TB;

    float s1 = 1.0f / sqrtf((float)D1);
    float s2 = 1.0f / sqrtf((float)D2);

    launch_pdl(proj1_kernel, gP1, TB, emb, Wq1, bq1, Wk1, bk1, Wv1, bv1, Ws1, bs1, N);
    launch_pdl(edge_fused_kernel<D1>, gE4, TB, src, dst, s1, E);
    launch_pdl(fin1_proj2_kernel, gFP, TB, Wq2, bq2, Wk2, bk2, Wv2, bv2, Ws2, bs2, N);
    launch_pdl(edge_fused_kernel<D2>, gE4, TB, src, dst, s2, E);
    launch_pdl(finalize2_out_kernel, gN2, TB, Wo, bo, out, N);
}

// round 14
// speedup vs baseline: 1.9772x; 1.7138x over previous
#include <cuda_runtime.h>
#include <math_constants.h>

#define N_NODES 100000
#define N_EDGES 1600000
#define D1 32
#define D2 16
#define FULL 0xffffffffu

// ---------------- scratch (device globals; no allocation allowed) -------------
__device__ __align__(16) float g_q   [N_NODES * D1];
__device__ __align__(16) float g_k   [N_NODES * D1];
__device__ __align__(16) float g_v   [N_NODES * D1];
__device__ __align__(16) float g_skip[N_NODES * D1];
__device__ __align__(16) float g_acc [N_NODES * D1];
__device__ __align__(16) float g_sk2 [N_NODES * D2];
__device__ float g_sum [N_NODES];

// ---------------- f32x2 packed-FMA helpers (B300 FFMA2 via PTX) ---------------
typedef unsigned long long u64;
__device__ __forceinline__ u64 pack2(float a, float b) {
    u64 r; asm("mov.b64 %0,{%1,%2};" : "=l"(r) : "f"(a), "f"(b)); return r;
}
__device__ __forceinline__ float2 unpk2(u64 p) {
    float2 r; asm("mov.b64 {%0,%1},%2;" : "=f"(r.x), "=f"(r.y) : "l"(p)); return r;
}
__device__ __forceinline__ u64 fma2(u64 a, u64 b, u64 c) {
    u64 r; asm("fma.rn.f32x2 %0,%1,%2,%3;" : "=l"(r) : "l"(a), "l"(b), "l"(c)); return r;
}
__device__ __forceinline__ u64 lds2(const float* p) {
    float2 v = *(const float2*)p;
    u64 r; asm("mov.b64 %0,{%1,%2};" : "=l"(r) : "f"(v.x), "f"(v.y)); return r;
}

__device__ __forceinline__ void redAdd4(float4* p, float a, float b, float c, float d) {
    asm volatile("red.global.add.v4.f32 [%0], {%1,%2,%3,%4};"
                 :: "l"(p), "f"(a), "f"(b), "f"(c), "f"(d) : "memory");
}

// ---------------- layer-1 projection (f32x2), fused acc/sum zeroing ----------
// 16 nodes/block; thread = (node ln, dim-pair jh). 4 FFMA2 per input dim.
__global__ __launch_bounds__(256) void proj1_kernel(
        const float* __restrict__ x,
        const float* __restrict__ Wq, const float* __restrict__ bq,
        const float* __restrict__ Wk, const float* __restrict__ bk,
        const float* __restrict__ Wv, const float* __restrict__ bv,
        const float* __restrict__ Ws, const float* __restrict__ bs,
        int n) {
    constexpr int NPB = 16;
    __shared__ __align__(16) float sW[4][D1 * D1];
    __shared__ __align__(16) float sx[NPB][D1];
    int t = threadIdx.x;
    for (int i = t; i < D1 * D1; i += 256) {
        sW[0][i] = Wq[i]; sW[1][i] = Wk[i]; sW[2][i] = Wv[i]; sW[3][i] = Ws[i];
    }
    int node0 = blockIdx.x * NPB;
    for (int i = t; i < NPB * D1; i += 256) {
        int nn = node0 + (i >> 5);
        sx[i >> 5][i & 31] = (nn < n) ? x[(size_t)nn * D1 + (i & 31)] : 0.0f;
    }
    __syncthreads();
    int ln = t >> 4;                  // 0..15
    int j  = (t & 15) * 2;            // even dim pair
    int node = node0 + ln;
    if (node >= n) return;
    u64 aq = pack2(bq[j], bq[j+1]);
    u64 ak = pack2(bk[j], bk[j+1]);
    u64 av = pack2(bv[j], bv[j+1]);
    u64 as = pack2(bs[j], bs[j+1]);
    #pragma unroll
    for (int i = 0; i < D1; i++) {
        float xi = sx[ln][i];
        u64 x2 = pack2(xi, xi);
        aq = fma2(x2, lds2(&sW[0][i * D1 + j]), aq);
        ak = fma2(x2, lds2(&sW[1][i * D1 + j]), ak);
        av = fma2(x2, lds2(&sW[2][i * D1 + j]), av);
        as = fma2(x2, lds2(&sW[3][i * D1 + j]), as);
    }
    int o = node * D1 + j;
    *(float2*)(g_q + o)    = unpk2(aq);
    *(float2*)(g_k + o)    = unpk2(ak);
    *(float2*)(g_v + o)    = unpk2(av);
    *(float2*)(g_skip + o) = unpk2(as);
    *(float2*)(g_acc + o)  = make_float2(0.0f, 0.0f);
    if (j == 0) g_sum[node] = 0.0f;
}

// ---------------- single fused edge pass (EXACT R5 form: 4 lanes/edge) -------
template<int D>
__global__ __launch_bounds__(256) void edge_fused_kernel(
        const int* __restrict__ src, const int* __restrict__ dst,
        float scale, int nE) {
    int tid = blockIdx.x * blockDim.x + threadIdx.x;
    int e = tid >> 2, lane = tid & 3;
    if (e >= nE) return;
    int s = src[e], d = dst[e];
    const float4* qr = (const float4*)(g_q + (size_t)d * D);
    const float4* kr = (const float4*)(g_k + (size_t)s * D);
    float acc = 0.0f;
    #pragma unroll
    for (int i = 0; i < D / 16; i++) {
        float4 a = qr[i * 4 + lane];
        float4 b = kr[i * 4 + lane];
        acc = fmaf(a.x, b.x, fmaf(a.y, b.y, fmaf(a.z, b.z, fmaf(a.w, b.w, acc))));
    }
    unsigned m = __activemask();
    acc += __shfl_xor_sync(m, acc, 1, 4);
    acc += __shfl_xor_sync(m, acc, 2, 4);
    float w = __expf(fminf(acc * scale, 75.0f));   // overflow guard only
    if (lane == 0) atomicAdd(g_sum + d, w);
    const float4* vr = (const float4*)(g_v + (size_t)s * D);
    float4*       ar = (float4*)(g_acc + (size_t)d * D);
    #pragma unroll
    for (int i = 0; i < D / 16; i++) {
        float4 t = vr[i * 4 + lane];
        redAdd4(ar + i * 4 + lane, t.x * w, t.y * w, t.z * w, t.w * w);
    }
}

// ---------------- fused: finalize layer 1 -> SMEM h -> layer-2 proj (f32x2) --
// 32 nodes/block. Phase A: float4 finalize into smem + re-zero. Phase B: 32->16
// projection with packed FFMA2; layer-2 q/k/v live in low halves of g_q/g_k/g_v.
__global__ __launch_bounds__(256) void fin1_proj2_kernel(
        const float* __restrict__ Wq, const float* __restrict__ bq,
        const float* __restrict__ Wk, const float* __restrict__ bk,
        const float* __restrict__ Wv, const float* __restrict__ bv,
        const float* __restrict__ Ws, const float* __restrict__ bs,
        int n) {
    constexpr int NPB = 32;
    __shared__ __align__(16) float sW[4][D1 * D2];
    __shared__ __align__(16) float sh[NPB][D1];
    int t = threadIdx.x;
    for (int i = t; i < D1 * D2; i += 256) {
        sW[0][i] = Wq[i]; sW[1][i] = Wk[i]; sW[2][i] = Wv[i]; sW[3][i] = Ws[i];
    }
    int node0 = blockIdx.x * NPB;
    {   // Phase A: 32 nodes * 32 dims = 1024 floats = 256 float4, 1 per thread
        int ln = t >> 3;
        int c  = (t & 7) * 4;
        int node = node0 + ln;
        if (node < n) {
            int o = node * D1 + c;
            float4 a4 = *(const float4*)(g_acc + o);
            float4 s4 = *(const float4*)(g_skip + o);
            float inv = 1.0f / (g_sum[node] + 1e-16f);
            float4 h;
            h.x = fmaxf(fmaf(a4.x, inv, s4.x), 0.0f);
            h.y = fmaxf(fmaf(a4.y, inv, s4.y), 0.0f);
            h.z = fmaxf(fmaf(a4.z, inv, s4.z), 0.0f);
            h.w = fmaxf(fmaf(a4.w, inv, s4.w), 0.0f);
            *(float4*)&sh[ln][c] = h;
            *(float4*)(g_acc + o) = make_float4(0.0f, 0.0f, 0.0f, 0.0f);
            if (c == 0) g_sum[node] = 0.0f;
        }
    }
    __syncthreads();
    // Phase B: thread = (node ln, dim-pair jh); 4 FFMA2 per input dim.
    int ln = t >> 3;                  // 0..31
    int j  = (t & 7) * 2;             // even dim pair in 0..15
    int node = node0 + ln;
    if (node >= n) return;
    u64 aq = pack2(bq[j], bq[j+1]);
    u64 ak = pack2(bk[j], bk[j+1]);
    u64 av = pack2(bv[j], bv[j+1]);
    u64 as = pack2(bs[j], bs[j+1]);
    #pragma unroll
    for (int i = 0; i < D1; i++) {
        float hi = sh[ln][i];
        u64 h2 = pack2(hi, hi);
        aq = fma2(h2, lds2(&sW[0][i * D2 + j]), aq);
        ak = fma2(h2, lds2(&sW[1][i * D2 + j]), ak);
        av = fma2(h2, lds2(&sW[2][i * D2 + j]), av);
        as = fma2(h2, lds2(&sW[3][i * D2 + j]), as);
    }
    int o = node * D2 + j;
    *(float2*)(g_q + o)   = unpk2(aq);
    *(float2*)(g_k + o)   = unpk2(ak);
    *(float2*)(g_v + o)   = unpk2(av);
    *(float2*)(g_sk2 + o) = unpk2(as);
}

// ---------------- finalize layer 2 + output linear (16 -> 2), fused ----------
__global__ __launch_bounds__(256) void finalize2_out_kernel(
        const float* __restrict__ Wo, const float* __restrict__ bo,
        float* __restrict__ out, int n) {
    int tid = blockIdx.x * blockDim.x + threadIdx.x;
    if (tid >= n * D2) return;
    int node = tid >> 4;
    int i = tid & 15;
    float val = g_acc[tid] / (g_sum[node] + 1e-16f) + g_sk2[tid];
    val = fmaxf(val, 0.0f);
    float p0 = val * Wo[i * 2 + 0];
    float p1 = val * Wo[i * 2 + 1];
    unsigned m = __activemask();
    #pragma unroll
    for (int o = 8; o; o >>= 1) {
        p0 += __shfl_xor_sync(m, p0, o, 16);
        p1 += __shfl_xor_sync(m, p1, o, 16);
    }
    if (i == 0) {
        out[node * 2 + 0] = p0 + bo[0];
        out[node * 2 + 1] = p1 + bo[1];
    }
}

// ---------------- launch ------------------------------------------------------
extern "C" void kernel_launch(void* const* d_in, const int* in_sizes, int n_in,
                              void* d_out, int out_size) {
    const int*   ei  = (const int*)d_in[0];
    const float* emb = (const float*)d_in[1];
    const float *Wq1 = (const float*)d_in[2],  *bq1 = (const float*)d_in[3];
    const float *Wk1 = (const float*)d_in[4],  *bk1 = (const float*)d_in[5];
    const float *Wv1 = (const float*)d_in[6],  *bv1 = (const float*)d_in[7];
    const float *Ws1 = (const float*)d_in[8],  *bs1 = (const float*)d_in[9];
    const float *Wq2 = (const float*)d_in[10], *bq2 = (const float*)d_in[11];
    const float *Wk2 = (const float*)d_in[12], *bk2 = (const float*)d_in[13];
    const float *Wv2 = (const float*)d_in[14], *bv2 = (const float*)d_in[15];
    const float *Ws2 = (const float*)d_in[16], *bs2 = (const float*)d_in[17];
    const float *Wo  = (const float*)d_in[18], *bo  = (const float*)d_in[19];
    float* out = (float*)d_out;

    int E = in_sizes[0] / 2;
    int N = in_sizes[1] / D1;
    const int* src = ei;
    const int* dst = ei + E;

    const int TB = 256;
    int gP1 = (N + 15) / 16;                   // 16 nodes / block
    int gE4 = (int)(((size_t)E * 4 + TB - 1) / TB);  // 4 lanes / edge
    int gFP = (N + 31) / 32;                   // 32 nodes / block
    int gN2 = (N * D2 + TB - 1) / TB;

    float s1 = 1.0f / sqrtf((float)D1);
    float s2 = 1.0f / sqrtf((float)D2);

    // ---- layer 1 (d=32) ----
    proj1_kernel<<<gP1, TB>>>(emb, Wq1, bq1, Wk1, bk1, Wv1, bv1, Ws1, bs1, N);
    edge_fused_kernel<D1><<<gE4, TB>>>(src, dst, s1, E);

    // ---- finalize 1 + projection 2 (fused) ----
    fin1_proj2_kernel<<<gFP, TB>>>(Wq2, bq2, Wk2, bk2, Wv2, bv2, Ws2, bs2, N);

    // ---- layer 2 (d=16) ----
    edge_fused_kernel<D2><<<gE4, TB>>>(src, dst, s2, E);
    finalize2_out_kernel<<<gN2, TB>>>(Wo, bo, out, N);
}